// round 16
// baseline (speedup 1.0000x reference)
#include <cuda_runtime.h>

// Shape (fixed by reference)
#define B_     16
#define T_     4096
#define D_     512
#define L_     64                 // t-steps per block tile
#define HALF_  32                 // t-steps per half
#define DG_    128                // d-lanes per block
#define NDG    (D_ / DG_)         // 4
#define C_     (T_ / L_)          // 64 chunks per chain
#define NCHAIN (B_ * NDG)         // 64 chains
#define NBLK   (NCHAIN * C_)      // 4096 blocks
#define THREADS 256

// Decoupled-lookback state (static __device__ scratch; flags re-zeroed per launch)
__device__ float2 g_agg [(size_t)NBLK * DG_];   // local aggregates   (4 MB)
__device__ float2 g_incl[(size_t)NBLK * DG_];   // inclusive prefixes (4 MB)
__device__ int    g_flag[NBLK];                 // 0=none, 1=agg, 2=inclusive

__global__ void init_flags_kernel()
{
    ((int4*)g_flag)[blockIdx.x * THREADS + threadIdx.x] =
        make_int4(0, 0, 0, 0);
}

// ---------------------------------------------------------------------------
// Warp-specialized decoupled-lookback scan (converged configuration).
//   bid = c*NCHAIN + chain (waves span all chains -> shallow lookback).
//   Warps 4-7 (h=1): tile load -> full 64-step local scan -> publish agg.
//   Warps 0-3 (h=0): lookback runs CONCURRENTLY with the scan.
//   One __syncthreads joins; both halves rescan from the true carry and
//   stream outputs. 32 KB smem x-stash -> x is read from DRAM exactly once.
//   Measured: 392 MB @ ~5.05 TB/s effective = mixed-stream HBM ceiling.
// ---------------------------------------------------------------------------
__global__ void __launch_bounds__(THREADS) scan_kernel(
    const float* __restrict__ x,
    const float* __restrict__ Ar,
    const float* __restrict__ Ai,
    float2* __restrict__ out)
{
    __shared__ float  sx[L_ * DG_];      // 32 KB x tile, [t][d]
    __shared__ float2 se0[DG_];          // state after half0 (zero-init scan)
    __shared__ float2 sagg[DG_];         // full-tile aggregate
    __shared__ float2 scarry[DG_];       // block carry from lookback

    const int tid   = threadIdx.x;
    const int bid   = blockIdx.x;
    const int chain = bid & (NCHAIN - 1);
    const int c     = bid >> 6;                 // / NCHAIN
    const int dg    = chain & (NDG - 1);
    const int b     = chain >> 2;               // / NDG
    const int d     = tid & (DG_ - 1);
    const int h     = tid >> 7;                 // 0: lookback+half0, 1: scan+half1
    const int dglob = dg * DG_ + d;

    const float ar = Ar[dglob];
    const float ai = Ai[dglob];

    // A^32 (5 squarings) and A^64 — cheap, computed by every thread.
    float p32r = ar, p32i = ai;
    #pragma unroll
    for (int k = 0; k < 5; ++k) {
        const float nr = p32r * p32r - p32i * p32i;
        const float ni = 2.0f * p32r * p32i;
        p32r = nr; p32i = ni;
    }
    const float p64r = p32r * p32r - p32i * p32i;
    const float p64i = 2.0f * p32r * p32i;

    if (h == 1) {
        // ===== producer half: tile load + local scan + agg publish ==========
        const float* xb = x + ((size_t)b * T_ + (size_t)c * L_) * D_ + dg * DG_;
        {
            const int lane4 = d & 31;           // float4 column (32 per row)
            const int rsub  = d >> 5;           // 0..3
            float4* s4 = (float4*)sx;
            #pragma unroll
            for (int r = 0; r < L_ / 4; ++r) {
                const int row = r * 4 + rsub;
                s4[row * (DG_ / 4) + lane4] =
                    __ldcs((const float4*)(xb + (size_t)row * D_) + lane4);
            }
        }
        asm volatile("bar.sync 1, 128;" ::: "memory");   // h1 group: tile ready

        const float* sxd = sx + d;
        float er = 0.0f, ei = 0.0f;
        #pragma unroll
        for (int t = 0; t < HALF_; ++t) {
            const float xv = sxd[t * DG_];
            const float nr = fmaf(er, ar, fmaf(-ei, ai, xv));
            const float ni = fmaf(er, ai, ei * ar);
            er = nr; ei = ni;
        }
        se0[d] = make_float2(er, ei);            // E0 = state after half0
        #pragma unroll
        for (int t = HALF_; t < L_; ++t) {
            const float xv = sxd[t * DG_];
            const float nr = fmaf(er, ar, fmaf(-ei, ai, xv));
            const float ni = fmaf(er, ai, ei * ar);
            er = nr; ei = ni;
        }
        sagg[d] = make_float2(er, ei);           // block aggregate

        if (c == 0) {                            // inclusive == aggregate
            g_incl[(size_t)bid * DG_ + d] = make_float2(er, ei);
            __threadfence();
            asm volatile("bar.sync 1, 128;" ::: "memory");
            if (d == 0) atomicExch(&g_flag[bid], 2);
        } else if (c < C_ - 1) {
            g_agg[(size_t)bid * DG_ + d] = make_float2(er, ei);
            __threadfence();
            asm volatile("bar.sync 1, 128;" ::: "memory");
            if (d == 0) atomicExch(&g_flag[bid], 1);
        }
    } else {
        // ===== lookback half: runs concurrently with the scan above =========
        float cr = 0.0f, ci = 0.0f;
        if (c > 0) {
            float mr = 1.0f, mi = 0.0f;          // running multiplier A^(64k)
            int j = bid - NCHAIN;                // predecessor chunk, same chain
            while (true) {
                volatile int* f = &g_flag[j];
                int v = *f;
                while (v == 0) { __nanosleep(40); v = *f; }
                __threadfence();                 // acquire
                const float2 val = (v == 2)
                    ? __ldcg(&g_incl[(size_t)j * DG_ + d])
                    : __ldcg(&g_agg [(size_t)j * DG_ + d]);
                cr = fmaf(mr, val.x, fmaf(-mi, val.y, cr));
                ci = fmaf(mi, val.x, fmaf( mr, val.y, ci));
                if (v == 2) break;               // prefix complete
                const float nmr = mr * p64r - mi * p64i;
                const float nmi = mr * p64i + mi * p64r;
                mr = nmr; mi = nmi;
                j -= NCHAIN;
            }
        }
        scarry[d] = make_float2(cr, ci);
    }

    __syncthreads();   // join: tile, E0, agg, carry all valid

    // ===== publish inclusive (h0, off the store path) ========================
    float hr, hi;
    if (h == 0) {
        const float2 cv = scarry[d];
        if (c > 0 && c < C_ - 1) {
            const float2 ag = sagg[d];
            const float inr = fmaf(p64r, cv.x, fmaf(-p64i, cv.y, ag.x));
            const float ini = fmaf(p64i, cv.x, fmaf( p64r, cv.y, ag.y));
            g_incl[(size_t)bid * DG_ + d] = make_float2(inr, ini);
            __threadfence();
            asm volatile("bar.sync 2, 128;" ::: "memory");
            if (d == 0) atomicExch(&g_flag[bid], 2);
        }
        hr = cv.x; hi = cv.y;                    // rescan half0 from carry
    } else {
        const float2 cv = scarry[d];
        const float2 e0 = se0[d];
        // carry into half1 = A^32 * carry + E0
        hr = fmaf(p32r, cv.x, fmaf(-p32i, cv.y, e0.x));
        hi = fmaf(p32i, cv.x, fmaf( p32r, cv.y, e0.y));
    }

    // ===== rescan my half from its true carry; stream outputs ================
    const float* sxh = sx + h * HALF_ * DG_ + d;
    float2* ob = out + ((size_t)b * T_ + (size_t)c * L_ + h * HALF_) * D_ + dglob;
    #pragma unroll
    for (int t = 0; t < HALF_; ++t) {
        const float xv = sxh[t * DG_];
        const float nr = fmaf(hr, ar, fmaf(-hi, ai, xv));
        const float ni = fmaf(hr, ai, hi * ar);
        hr = nr; hi = ni;
        __stcs(&ob[(size_t)t * D_], make_float2(nr, ni));
    }
}

// ---------------------------------------------------------------------------
// Inputs (metadata order): x [B*T*D] f32, A_real [D] f32, A_imag [D] f32.
// Output: [B, T, D, 2] f32.
// ---------------------------------------------------------------------------
extern "C" void kernel_launch(void* const* d_in, const int* in_sizes, int n_in,
                              void* d_out, int out_size)
{
    const float* x  = (const float*)d_in[0];
    const float* Ar = (const float*)d_in[1];
    const float* Ai = (const float*)d_in[2];
    float2* out = (float2*)d_out;

    init_flags_kernel<<<NBLK / (THREADS * 4), THREADS>>>();
    scan_kernel<<<NBLK, THREADS>>>(x, Ar, Ai, out);
}

// round 17
// speedup vs baseline: 1.0051x; 1.0051x over previous
#include <cuda_runtime.h>

// Shape (fixed by reference)
#define B_     16
#define T_     4096
#define D_     512
#define L_     64                 // t-steps per block tile
#define HALF_  32                 // t-steps per half
#define DG_    128                // d-lanes per block
#define NDG    (D_ / DG_)         // 4
#define C_     (T_ / L_)          // 64 chunks per chain
#define NCHAIN (B_ * NDG)         // 64 chains
#define NBLK   (NCHAIN * C_)      // 4096 blocks
#define THREADS 256

// Decoupled-lookback state (static __device__ scratch; flags re-zeroed per launch)
__device__ float2 g_agg [(size_t)NBLK * DG_];   // local aggregates   (4 MB)
__device__ float2 g_incl[(size_t)NBLK * DG_];   // inclusive prefixes (4 MB)
__device__ int    g_flag[NBLK];                 // 0=none, 1=agg, 2=inclusive

__global__ void init_flags_kernel()
{
    ((int4*)g_flag)[blockIdx.x * THREADS + threadIdx.x] =
        make_int4(0, 0, 0, 0);
}

// ---------------------------------------------------------------------------
// Warp-specialized decoupled-lookback scan (converged configuration).
//   bid = c*NCHAIN + chain (waves span all chains -> shallow lookback).
//   Warps 4-7 (h=1): tile load -> full 64-step local scan -> publish agg.
//   Warps 0-3 (h=0): lookback runs CONCURRENTLY with the scan.
//   One __syncthreads joins; both halves rescan from the true carry and
//   stream outputs. 32 KB smem x-stash -> x is read from DRAM exactly once.
//   Measured: 392 MB @ ~5.05 TB/s effective = mixed-stream HBM ceiling.
// ---------------------------------------------------------------------------
__global__ void __launch_bounds__(THREADS) scan_kernel(
    const float* __restrict__ x,
    const float* __restrict__ Ar,
    const float* __restrict__ Ai,
    float2* __restrict__ out)
{
    __shared__ float  sx[L_ * DG_];      // 32 KB x tile, [t][d]
    __shared__ float2 se0[DG_];          // state after half0 (zero-init scan)
    __shared__ float2 sagg[DG_];         // full-tile aggregate
    __shared__ float2 scarry[DG_];       // block carry from lookback

    const int tid   = threadIdx.x;
    const int bid   = blockIdx.x;
    const int chain = bid & (NCHAIN - 1);
    const int c     = bid >> 6;                 // / NCHAIN
    const int dg    = chain & (NDG - 1);
    const int b     = chain >> 2;               // / NDG
    const int d     = tid & (DG_ - 1);
    const int h     = tid >> 7;                 // 0: lookback+half0, 1: scan+half1
    const int dglob = dg * DG_ + d;

    const float ar = Ar[dglob];
    const float ai = Ai[dglob];

    // A^32 (5 squarings) and A^64 — cheap, computed by every thread.
    float p32r = ar, p32i = ai;
    #pragma unroll
    for (int k = 0; k < 5; ++k) {
        const float nr = p32r * p32r - p32i * p32i;
        const float ni = 2.0f * p32r * p32i;
        p32r = nr; p32i = ni;
    }
    const float p64r = p32r * p32r - p32i * p32i;
    const float p64i = 2.0f * p32r * p32i;

    if (h == 1) {
        // ===== producer half: tile load + local scan + agg publish ==========
        const float* xb = x + ((size_t)b * T_ + (size_t)c * L_) * D_ + dg * DG_;
        {
            const int lane4 = d & 31;           // float4 column (32 per row)
            const int rsub  = d >> 5;           // 0..3
            float4* s4 = (float4*)sx;
            #pragma unroll
            for (int r = 0; r < L_ / 4; ++r) {
                const int row = r * 4 + rsub;
                s4[row * (DG_ / 4) + lane4] =
                    __ldcs((const float4*)(xb + (size_t)row * D_) + lane4);
            }
        }
        asm volatile("bar.sync 1, 128;" ::: "memory");   // h1 group: tile ready

        const float* sxd = sx + d;
        float er = 0.0f, ei = 0.0f;
        #pragma unroll
        for (int t = 0; t < HALF_; ++t) {
            const float xv = sxd[t * DG_];
            const float nr = fmaf(er, ar, fmaf(-ei, ai, xv));
            const float ni = fmaf(er, ai, ei * ar);
            er = nr; ei = ni;
        }
        se0[d] = make_float2(er, ei);            // E0 = state after half0
        #pragma unroll
        for (int t = HALF_; t < L_; ++t) {
            const float xv = sxd[t * DG_];
            const float nr = fmaf(er, ar, fmaf(-ei, ai, xv));
            const float ni = fmaf(er, ai, ei * ar);
            er = nr; ei = ni;
        }
        sagg[d] = make_float2(er, ei);           // block aggregate

        if (c == 0) {                            // inclusive == aggregate
            g_incl[(size_t)bid * DG_ + d] = make_float2(er, ei);
            __threadfence();
            asm volatile("bar.sync 1, 128;" ::: "memory");
            if (d == 0) atomicExch(&g_flag[bid], 2);
        } else if (c < C_ - 1) {
            g_agg[(size_t)bid * DG_ + d] = make_float2(er, ei);
            __threadfence();
            asm volatile("bar.sync 1, 128;" ::: "memory");
            if (d == 0) atomicExch(&g_flag[bid], 1);
        }
    } else {
        // ===== lookback half: runs concurrently with the scan above =========
        float cr = 0.0f, ci = 0.0f;
        if (c > 0) {
            float mr = 1.0f, mi = 0.0f;          // running multiplier A^(64k)
            int j = bid - NCHAIN;                // predecessor chunk, same chain
            while (true) {
                volatile int* f = &g_flag[j];
                int v = *f;
                while (v == 0) { __nanosleep(40); v = *f; }
                __threadfence();                 // acquire
                const float2 val = (v == 2)
                    ? __ldcg(&g_incl[(size_t)j * DG_ + d])
                    : __ldcg(&g_agg [(size_t)j * DG_ + d]);
                cr = fmaf(mr, val.x, fmaf(-mi, val.y, cr));
                ci = fmaf(mi, val.x, fmaf( mr, val.y, ci));
                if (v == 2) break;               // prefix complete
                const float nmr = mr * p64r - mi * p64i;
                const float nmi = mr * p64i + mi * p64r;
                mr = nmr; mi = nmi;
                j -= NCHAIN;
            }
        }
        scarry[d] = make_float2(cr, ci);
    }

    __syncthreads();   // join: tile, E0, agg, carry all valid

    // ===== publish inclusive (h0, off the store path) ========================
    float hr, hi;
    if (h == 0) {
        const float2 cv = scarry[d];
        if (c > 0 && c < C_ - 1) {
            const float2 ag = sagg[d];
            const float inr = fmaf(p64r, cv.x, fmaf(-p64i, cv.y, ag.x));
            const float ini = fmaf(p64i, cv.x, fmaf( p64r, cv.y, ag.y));
            g_incl[(size_t)bid * DG_ + d] = make_float2(inr, ini);
            __threadfence();
            asm volatile("bar.sync 2, 128;" ::: "memory");
            if (d == 0) atomicExch(&g_flag[bid], 2);
        }
        hr = cv.x; hi = cv.y;                    // rescan half0 from carry
    } else {
        const float2 cv = scarry[d];
        const float2 e0 = se0[d];
        // carry into half1 = A^32 * carry + E0
        hr = fmaf(p32r, cv.x, fmaf(-p32i, cv.y, e0.x));
        hi = fmaf(p32i, cv.x, fmaf( p32r, cv.y, e0.y));
    }

    // ===== rescan my half from its true carry; stream outputs ================
    const float* sxh = sx + h * HALF_ * DG_ + d;
    float2* ob = out + ((size_t)b * T_ + (size_t)c * L_ + h * HALF_) * D_ + dglob;
    #pragma unroll
    for (int t = 0; t < HALF_; ++t) {
        const float xv = sxh[t * DG_];
        const float nr = fmaf(hr, ar, fmaf(-hi, ai, xv));
        const float ni = fmaf(hr, ai, hi * ar);
        hr = nr; hi = ni;
        __stcs(&ob[(size_t)t * D_], make_float2(nr, ni));
    }
}

// ---------------------------------------------------------------------------
// Inputs (metadata order): x [B*T*D] f32, A_real [D] f32, A_imag [D] f32.
// Output: [B, T, D, 2] f32.
// ---------------------------------------------------------------------------
extern "C" void kernel_launch(void* const* d_in, const int* in_sizes, int n_in,
                              void* d_out, int out_size)
{
    const float* x  = (const float*)d_in[0];
    const float* Ar = (const float*)d_in[1];
    const float* Ai = (const float*)d_in[2];
    float2* out = (float2*)d_out;

    init_flags_kernel<<<NBLK / (THREADS * 4), THREADS>>>();
    scan_kernel<<<NBLK, THREADS>>>(x, Ar, Ai, out);
}